// round 12
// baseline (speedup 1.0000x reference)
#include <cuda_runtime.h>
#include <cuda_fp16.h>

// GCN: embedding mean-pool -> GraphConv(128->128, relu) -> GraphConv(128->40)
// embT = emb@W1 reorder; pull-based CSR (uint16); fp16 CG staging.
// R12: deeper MLP on the latency-bound gathers — layer1 MLP-8 @ 3 blocks/SM
// (49KB in flight > 38KB LTS latency-BW product), spmm2 MLP-8, embed ring-5.

#define NN   50000
#define NE   800000
#define FD   128
#define SEQ  20
#define CLS  40
#define VOC  32000
#define NB   ((NN + 255) / 256)      // 196
#define GEMMB 296
#define DEGB  ((NE + 255) / 256)     // 3125
#define EMBB  (NN / 8)               // 6250

static __device__ uint2 g_embT[(size_t)VOC * 32];   // emb@W1, fp16 CG layout
static __device__ uint2 g_hA[(size_t)NN * 32];      // pooled feats, fp16 CG
static __device__ __half g_yh[(size_t)NN * CLS];
static __device__ int   g_odeg[NN];
static __device__ int   g_ideg[NN];
static __device__ float g_rso[NN];
static __device__ float g_rsi[NN];
static __device__ int   g_off[NN + 1];
static __device__ int   g_cur[NN];
static __device__ unsigned short g_csr[NE];
static __device__ int   g_btot[256];
static __device__ int   g_arrive;

__device__ __forceinline__ unsigned long long pack2(float lo, float hi) {
    unsigned long long r;
    asm("mov.b64 %0, {%1, %2};" : "=l"(r) : "f"(lo), "f"(hi));
    return r;
}
__device__ __forceinline__ float2 unpack2(unsigned long long v) {
    float lo, hi;
    asm("mov.b64 {%0, %1}, %2;" : "=f"(lo), "=f"(hi) : "l"(v));
    return make_float2(lo, hi);
}
__device__ __forceinline__ void ffma2(unsigned long long& d,
                                      unsigned long long a,
                                      unsigned long long b) {
    asm("fma.rn.f32x2 %0, %1, %2, %0;" : "+l"(d) : "l"(a), "l"(b));
}
__device__ __forceinline__ void acc_cg(float2& lo, float2& hi, uint2 raw) {
    float2 f0 = __half22float2(*(__half2*)&raw.x);
    float2 f1 = __half22float2(*(__half2*)&raw.y);
    lo.x += f0.x; lo.y += f0.y; hi.x += f1.x; hi.y += f1.y;
}

__global__ __launch_bounds__(256) void k_zero() {
    int i = blockIdx.x * 256 + threadIdx.x;
    if (i < NN) { g_odeg[i] = 0; g_ideg[i] = 0; g_cur[i] = 0; }
    if (i == 0) g_arrive = 0;
}

// blocks [0,GEMMB): embT = emb @ W1 -> fp16 CG (W1 k-half pairs in smem)
// blocks [GEMMB, GEMMB+DEGB): degree atomics (one pass over edges)
__global__ __launch_bounds__(256) void k_tabledeg(const float* __restrict__ emb,
                                                  const float* __restrict__ W1,
                                                  const int* __restrict__ src,
                                                  const int* __restrict__ dst) {
    if (blockIdx.x >= GEMMB) {
        int e = (blockIdx.x - GEMMB) * 256 + threadIdx.x;
        if (e < NE) {
            atomicAdd(&g_odeg[src[e]], 1);
            atomicAdd(&g_ideg[dst[e]], 1);
        }
        return;
    }
    extern __shared__ unsigned long long sW1p[];      // 64*128 u64 = 64KB
    for (int i = threadIdx.x; i < 64 * 128; i += 256) {
        int kp = i >> 7, c = i & 127;
        sW1p[i] = pack2(W1[kp * FD + c], W1[(kp + 64) * FD + c]);
    }
    __syncthreads();
    int warp = threadIdx.x >> 5, lane = threadIdx.x & 31;
    const int nwarps = GEMMB * 8;
    for (int b = blockIdx.x * 8 + warp; b < VOC / 4; b += nwarps) {
        unsigned long long px0[4], px1[4];
#pragma unroll
        for (int j = 0; j < 4; ++j) {
            int v = b * 4 + j;
            const float* row = emb + (long)v * FD;
            float2 a = *(const float2*)(row + 2 * lane);
            float2 c = *(const float2*)(row + 64 + 2 * lane);
            px0[j] = pack2(a.x, c.x);
            px1[j] = pack2(a.y, c.y);
        }
        unsigned long long acc[4][4];
#pragma unroll
        for (int j = 0; j < 4; ++j)
#pragma unroll
            for (int c = 0; c < 4; ++c) acc[j][c] = 0ull;
#pragma unroll 2
        for (int g = 0; g < 32; ++g) {
            const ulonglong2* w0 = (const ulonglong2*)&sW1p[(2 * g) * FD];
            const ulonglong2* w1 = (const ulonglong2*)&sW1p[(2 * g + 1) * FD];
            ulonglong2 wlo0 = w0[lane], whi0 = w0[32 + lane];
            ulonglong2 wlo1 = w1[lane], whi1 = w1[32 + lane];
#pragma unroll
            for (int j = 0; j < 4; ++j) {
                unsigned long long b0 = __shfl_sync(0xffffffffu, px0[j], g);
                ffma2(acc[j][0], b0, wlo0.x); ffma2(acc[j][1], b0, wlo0.y);
                ffma2(acc[j][2], b0, whi0.x); ffma2(acc[j][3], b0, whi0.y);
                unsigned long long b1v = __shfl_sync(0xffffffffu, px1[j], g);
                ffma2(acc[j][0], b1v, wlo1.x); ffma2(acc[j][1], b1v, wlo1.y);
                ffma2(acc[j][2], b1v, whi1.x); ffma2(acc[j][3], b1v, whi1.y);
            }
        }
#pragma unroll
        for (int j = 0; j < 4; ++j) {
            int v = b * 4 + j;
            float2 u0 = unpack2(acc[j][0]), u1 = unpack2(acc[j][1]);
            float2 u2 = unpack2(acc[j][2]), u3 = unpack2(acc[j][3]);
            __half2 h01 = __floats2half2_rn(u0.x + u0.y, u1.x + u1.y);
            __half2 h23 = __floats2half2_rn(u2.x + u2.y, u3.x + u3.y);
            uint2 o;
            o.x = *(unsigned*)&h01;
            o.y = *(unsigned*)&h23;
            g_embT[(long)v * 32 + lane] = o;
        }
    }
}

// Single-launch exclusive scan of g_ideg -> g_off, plus rso/rsi.
// 196 blocks co-resident -> spin barrier safe.
__global__ __launch_bounds__(256) void k_scan() {
    __shared__ int s[256];
    int tid = threadIdx.x;
    int i = blockIdx.x * 256 + tid;
    int v = (i < NN) ? g_ideg[i] : 0;
    s[tid] = v; __syncthreads();
#pragma unroll
    for (int st = 1; st < 256; st <<= 1) {
        int t = (tid >= st) ? s[tid - st] : 0;
        __syncthreads();
        s[tid] += t;
        __syncthreads();
    }
    int local_ex = s[tid] - v;
    if (tid == 255) g_btot[blockIdx.x] = s[255];
    __syncthreads();
    if (tid == 0) {
        __threadfence();
        atomicAdd(&g_arrive, 1);
        while (atomicAdd(&g_arrive, 0) < (int)gridDim.x) {}
        __threadfence();
    }
    __syncthreads();
    int pv = (tid < (int)blockIdx.x) ? g_btot[tid] : 0;
    s[tid] = pv; __syncthreads();
#pragma unroll
    for (int st = 128; st > 0; st >>= 1) {
        if (tid < st) s[tid] += s[tid + st];
        __syncthreads();
    }
    int prefix = s[0];
    if (i < NN) {
        g_off[i] = local_ex + prefix;
        g_rso[i] = rsqrtf((float)max(g_odeg[i], 1));
        g_rsi[i] = rsqrtf((float)max(g_ideg[i], 1));
    }
    if (i == 0) g_off[NN] = NE;
}

// blocks [0,EMBB): warp per node, ring-5 pipelined mean-pool of embT rows.
// blocks [EMBB, ...): CSR fill (uint16 src ids)
__global__ __launch_bounds__(256) void k_fillembed(const int* __restrict__ feat,
                                                   const int* __restrict__ src,
                                                   const int* __restrict__ dst) {
    if (blockIdx.x >= EMBB) {
        int e = (blockIdx.x - EMBB) * 256 + threadIdx.x;
        if (e < NE) {
            int d = dst[e];
            int p = g_off[d] + atomicAdd(&g_cur[d], 1);
            g_csr[p] = (unsigned short)src[e];
        }
        return;
    }
    int w    = (blockIdx.x * 256 + threadIdx.x) >> 5;
    int lane = threadIdx.x & 31;
    int tok = 0;
    if (lane < SEQ) tok = feat[w * SEQ + lane];
    unsigned nzm = __ballot_sync(0xffffffffu, (lane < SEQ) && (tok != 0));
    float inv_cnt = 1.0f / (float)max(__popc(nzm), 1);
    float2 lo = make_float2(0.f, 0.f), hi = make_float2(0.f, 0.f);
#pragma unroll
    for (int g = 0; g < SEQ / 5; ++g) {      // 4 groups of 5 rows in flight
        uint2 r[5];
#pragma unroll
        for (int j = 0; j < 5; ++j) {
            int tk = __shfl_sync(0xffffffffu, tok, 5 * g + j);
            r[j] = g_embT[(long)tk * 32 + lane];
        }
#pragma unroll
        for (int j = 0; j < 5; ++j) acc_cg(lo, hi, r[j]);
    }
    float sc = g_rso[w] * inv_cnt;
    __half2 h01 = __floats2half2_rn(lo.x * sc, lo.y * sc);
    __half2 h23 = __floats2half2_rn(hi.x * sc, hi.y * sc);
    uint2 o;
    o.x = *(unsigned*)&h01;
    o.y = *(unsigned*)&h23;
    g_hA[(long)w * 32 + lane] = o;
}

// Layer1: warp handles 4 dst nodes. Gather with 8-way MLP unroll;
// 3 blocks/SM (85-reg cap) -> 24 warps * 8 * 256B = 49KB in flight/SM.
__global__ __launch_bounds__(256, 3) void k_layer1(const float* __restrict__ b1,
                                                   const float* __restrict__ W2) {
    __shared__ unsigned long long sW2p[64 * 64];      // 32KB
    for (int i = threadIdx.x; i < 64 * 64; i += 256) {
        int kp = i >> 6, c = i & 63;
        float lo = (c < CLS) ? W2[kp * CLS + c] : 0.f;
        float hi = (c < CLS) ? W2[(kp + 64) * CLS + c] : 0.f;
        sW2p[i] = pack2(lo, hi);
    }
    __syncthreads();
    int warp = threadIdx.x >> 5, lane = threadIdx.x & 31;
    float2 blo = ((const float2*)b1)[lane];
    float2 bhi = ((const float2*)(b1 + 64))[lane];
    int nwarps = gridDim.x * 8;
    for (int b = blockIdx.x * 8 + warp; b < NN / 4; b += nwarps) {
        unsigned long long pp0[4], pp1[4];
#pragma unroll
        for (int j = 0; j < 4; ++j) {
            int d = b * 4 + j;
            int beg = g_off[d], end = g_off[d + 1];
            float2 lo = make_float2(0.f, 0.f), hi = make_float2(0.f, 0.f);
            for (int base = beg; base < end; base += 32) {
                int n = min(32, end - base);
                int sid = (base + lane < end) ? (int)g_csr[base + lane] : 0;
                int t = 0;
                for (; t + 8 <= n; t += 8) {
                    uint2 r[8];
#pragma unroll
                    for (int q = 0; q < 8; ++q) {
                        int s = __shfl_sync(0xffffffffu, sid, t + q);
                        r[q] = g_hA[(long)s * 32 + lane];
                    }
#pragma unroll
                    for (int q = 0; q < 8; ++q) acc_cg(lo, hi, r[q]);
                }
                for (; t + 4 <= n; t += 4) {
                    uint2 r[4];
#pragma unroll
                    for (int q = 0; q < 4; ++q) {
                        int s = __shfl_sync(0xffffffffu, sid, t + q);
                        r[q] = g_hA[(long)s * 32 + lane];
                    }
#pragma unroll
                    for (int q = 0; q < 4; ++q) acc_cg(lo, hi, r[q]);
                }
                for (; t < n; ++t) {
                    int s = __shfl_sync(0xffffffffu, sid, t);
                    acc_cg(lo, hi, g_hA[(long)s * 32 + lane]);
                }
            }
            float rin = g_rsi[d];
            float ro  = g_rso[d];
            float o0 = fmaxf(lo.x * rin + blo.x, 0.f) * ro;
            float o1 = fmaxf(lo.y * rin + blo.y, 0.f) * ro;
            float o2 = fmaxf(hi.x * rin + bhi.x, 0.f) * ro;
            float o3 = fmaxf(hi.y * rin + bhi.y, 0.f) * ro;
            pp0[j] = pack2(o0, o2);
            pp1[j] = pack2(o1, o3);
        }
        unsigned long long ay[4][2];
#pragma unroll
        for (int j = 0; j < 4; ++j) { ay[j][0] = 0ull; ay[j][1] = 0ull; }
#pragma unroll 2
        for (int g = 0; g < 32; ++g) {
            unsigned long long wa0 = sW2p[(2 * g) * 64 + lane];
            unsigned long long wb0 = sW2p[(2 * g) * 64 + 32 + lane];
            unsigned long long wa1 = sW2p[(2 * g + 1) * 64 + lane];
            unsigned long long wb1 = sW2p[(2 * g + 1) * 64 + 32 + lane];
#pragma unroll
            for (int j = 0; j < 4; ++j) {
                unsigned long long c0 = __shfl_sync(0xffffffffu, pp0[j], g);
                ffma2(ay[j][0], c0, wa0); ffma2(ay[j][1], c0, wb0);
                unsigned long long c1 = __shfl_sync(0xffffffffu, pp1[j], g);
                ffma2(ay[j][0], c1, wa1); ffma2(ay[j][1], c1, wb1);
            }
        }
#pragma unroll
        for (int j = 0; j < 4; ++j) {
            int d = b * 4 + j;
            float2 v0 = unpack2(ay[j][0]);
            float2 v1 = unpack2(ay[j][1]);
            __half* yr = g_yh + (long)d * CLS;
            yr[lane] = __float2half_rn(v0.x + v0.y);
            if (lane < 8) yr[32 + lane] = __float2half_rn(v1.x + v1.y);
        }
    }
}

// Layer-2 aggregation with 8-way MLP unroll: lane<20 owns uint pair.
__global__ __launch_bounds__(256, 4) void k_spmm2(const float* __restrict__ b2,
                                                  float* __restrict__ out) {
    int warp = threadIdx.x >> 5, lane = threadIdx.x & 31;
    int d = blockIdx.x * 8 + warp;
    if (d >= NN) return;
    int beg = g_off[d], end = g_off[d + 1];
    float ax = 0.f, ay = 0.f;
    const unsigned* Y = (const unsigned*)g_yh;
    for (int base = beg; base < end; base += 32) {
        int n = min(32, end - base);
        int sid = (base + lane < end) ? (int)g_csr[base + lane] : 0;
        int t = 0;
        for (; t + 8 <= n; t += 8) {
            unsigned u[8];
#pragma unroll
            for (int q = 0; q < 8; ++q) {
                int s = __shfl_sync(0xffffffffu, sid, t + q);
                u[q] = (lane < 20) ? Y[s * 20 + lane] : 0u;
            }
            if (lane < 20) {
#pragma unroll
                for (int q = 0; q < 8; ++q) {
                    float2 f = __half22float2(*(__half2*)&u[q]);
                    ax += f.x; ay += f.y;
                }
            }
        }
        for (; t < n; ++t) {
            int s = __shfl_sync(0xffffffffu, sid, t);
            if (lane < 20) {
                unsigned uu = Y[s * 20 + lane];
                float2 f = __half22float2(*(__half2*)&uu);
                ax += f.x; ay += f.y;
            }
        }
    }
    if (lane < 20) {
        float rin = g_rsi[d];
        float2 bp = ((const float2*)b2)[lane];
        ((float2*)(out + (long)d * CLS))[lane] =
            make_float2(ax * rin + bp.x, ay * rin + bp.y);
    }
}

extern "C" void kernel_launch(void* const* d_in, const int* in_sizes, int n_in,
                              void* d_out, int out_size) {
    const int*   feat = (const int*)  d_in[0];
    const int*   src  = (const int*)  d_in[1];
    const int*   dst  = (const int*)  d_in[2];
    const float* emb  = (const float*)d_in[3];
    const float* W1   = (const float*)d_in[4];
    const float* b1   = (const float*)d_in[5];
    const float* W2   = (const float*)d_in[6];
    const float* b2   = (const float*)d_in[7];
    float* out = (float*)d_out;

    const int smemT = 64 * 128 * 8;   // 64KB
    cudaFuncSetAttribute(k_tabledeg,
                         cudaFuncAttributeMaxDynamicSharedMemorySize, smemT);

    k_zero<<<NB, 256>>>();
    k_tabledeg<<<GEMMB + DEGB, 256, smemT>>>(emb, W1, src, dst);
    k_scan<<<NB, 256>>>();
    k_fillembed<<<EMBB + DEGB, 256>>>(feat, src, dst);
    k_layer1<<<444, 256>>>(b1, W2);   // 3 blocks/SM
    k_spmm2<<<NN / 8, 256>>>(b2, out);
}

// round 16
// speedup vs baseline: 1.0316x; 1.0316x over previous
#include <cuda_runtime.h>
#include <cuda_fp16.h>

// GCN: embedding mean-pool -> GraphConv(128->128, relu) -> GraphConv(128->40)
// embT = emb@W1 reorder; pull-based CSR (uint16); fp16 CG staging.
// R13 = R11 (proven best: MLP-4 gathers @ full occupancy — R9/R12 showed
// deeper MLP bought with occupancy always loses) minus the k_zero launch:
// the tail kernel re-zeroes the scratch arrays, restoring the module-load
// zero-state invariant for the next (deterministic) invocation.

#define NN   50000
#define NE   800000
#define FD   128
#define SEQ  20
#define CLS  40
#define VOC  32000
#define NB   ((NN + 255) / 256)      // 196
#define GEMMB 296
#define DEGB  ((NE + 255) / 256)     // 3125
#define EMBB  (NN / 8)               // 6250

static __device__ uint2 g_embT[(size_t)VOC * 32];   // emb@W1, fp16 CG layout
static __device__ uint2 g_hA[(size_t)NN * 32];      // pooled feats, fp16 CG
static __device__ __half g_yh[(size_t)NN * CLS];
static __device__ int   g_odeg[NN];                 // zero at kernel_launch entry
static __device__ int   g_ideg[NN];                 // (module-load init + tail reset)
static __device__ int   g_cur[NN];
static __device__ float g_rso[NN];
static __device__ float g_rsi[NN];
static __device__ int   g_off[NN + 1];
static __device__ unsigned short g_csr[NE];
static __device__ int   g_btot[256];
static __device__ int   g_arrive;

__device__ __forceinline__ unsigned long long pack2(float lo, float hi) {
    unsigned long long r;
    asm("mov.b64 %0, {%1, %2};" : "=l"(r) : "f"(lo), "f"(hi));
    return r;
}
__device__ __forceinline__ float2 unpack2(unsigned long long v) {
    float lo, hi;
    asm("mov.b64 {%0, %1}, %2;" : "=f"(lo), "=f"(hi) : "l"(v));
    return make_float2(lo, hi);
}
__device__ __forceinline__ void ffma2(unsigned long long& d,
                                      unsigned long long a,
                                      unsigned long long b) {
    asm("fma.rn.f32x2 %0, %1, %2, %0;" : "+l"(d) : "l"(a), "l"(b));
}
__device__ __forceinline__ void acc_cg(float2& lo, float2& hi, uint2 raw) {
    float2 f0 = __half22float2(*(__half2*)&raw.x);
    float2 f1 = __half22float2(*(__half2*)&raw.y);
    lo.x += f0.x; lo.y += f0.y; hi.x += f1.x; hi.y += f1.y;
}

// blocks [0,GEMMB): embT = emb @ W1 -> fp16 CG (W1 k-half pairs in smem)
// blocks [GEMMB, GEMMB+DEGB): degree atomics (arrays are pre-zeroed by the
// tail of the previous invocation / module load)
__global__ __launch_bounds__(256) void k_tabledeg(const float* __restrict__ emb,
                                                  const float* __restrict__ W1,
                                                  const int* __restrict__ src,
                                                  const int* __restrict__ dst) {
    if (blockIdx.x >= GEMMB) {
        int e = (blockIdx.x - GEMMB) * 256 + threadIdx.x;
        if (e < NE) {
            atomicAdd(&g_odeg[src[e]], 1);
            atomicAdd(&g_ideg[dst[e]], 1);
        }
        return;
    }
    extern __shared__ unsigned long long sW1p[];      // 64*128 u64 = 64KB
    for (int i = threadIdx.x; i < 64 * 128; i += 256) {
        int kp = i >> 7, c = i & 127;
        sW1p[i] = pack2(W1[kp * FD + c], W1[(kp + 64) * FD + c]);
    }
    __syncthreads();
    int warp = threadIdx.x >> 5, lane = threadIdx.x & 31;
    const int nwarps = GEMMB * 8;
    for (int b = blockIdx.x * 8 + warp; b < VOC / 4; b += nwarps) {
        unsigned long long px0[4], px1[4];
#pragma unroll
        for (int j = 0; j < 4; ++j) {
            int v = b * 4 + j;
            const float* row = emb + (long)v * FD;
            float2 a = *(const float2*)(row + 2 * lane);
            float2 c = *(const float2*)(row + 64 + 2 * lane);
            px0[j] = pack2(a.x, c.x);
            px1[j] = pack2(a.y, c.y);
        }
        unsigned long long acc[4][4];
#pragma unroll
        for (int j = 0; j < 4; ++j)
#pragma unroll
            for (int c = 0; c < 4; ++c) acc[j][c] = 0ull;
#pragma unroll 2
        for (int g = 0; g < 32; ++g) {
            const ulonglong2* w0 = (const ulonglong2*)&sW1p[(2 * g) * FD];
            const ulonglong2* w1 = (const ulonglong2*)&sW1p[(2 * g + 1) * FD];
            ulonglong2 wlo0 = w0[lane], whi0 = w0[32 + lane];
            ulonglong2 wlo1 = w1[lane], whi1 = w1[32 + lane];
#pragma unroll
            for (int j = 0; j < 4; ++j) {
                unsigned long long b0 = __shfl_sync(0xffffffffu, px0[j], g);
                ffma2(acc[j][0], b0, wlo0.x); ffma2(acc[j][1], b0, wlo0.y);
                ffma2(acc[j][2], b0, whi0.x); ffma2(acc[j][3], b0, whi0.y);
                unsigned long long b1v = __shfl_sync(0xffffffffu, px1[j], g);
                ffma2(acc[j][0], b1v, wlo1.x); ffma2(acc[j][1], b1v, wlo1.y);
                ffma2(acc[j][2], b1v, whi1.x); ffma2(acc[j][3], b1v, whi1.y);
            }
        }
#pragma unroll
        for (int j = 0; j < 4; ++j) {
            int v = b * 4 + j;
            float2 u0 = unpack2(acc[j][0]), u1 = unpack2(acc[j][1]);
            float2 u2 = unpack2(acc[j][2]), u3 = unpack2(acc[j][3]);
            __half2 h01 = __floats2half2_rn(u0.x + u0.y, u1.x + u1.y);
            __half2 h23 = __floats2half2_rn(u2.x + u2.y, u3.x + u3.y);
            uint2 o;
            o.x = *(unsigned*)&h01;
            o.y = *(unsigned*)&h23;
            g_embT[(long)v * 32 + lane] = o;
        }
    }
}

// Single-launch exclusive scan of g_ideg -> g_off, plus rso/rsi.
// 196 blocks co-resident -> spin barrier safe. Also seeds g_cur[i]=0 spot
// (already zero via invariant; left untouched here).
__global__ __launch_bounds__(256) void k_scan() {
    __shared__ int s[256];
    int tid = threadIdx.x;
    int i = blockIdx.x * 256 + tid;
    int v = (i < NN) ? g_ideg[i] : 0;
    s[tid] = v; __syncthreads();
#pragma unroll
    for (int st = 1; st < 256; st <<= 1) {
        int t = (tid >= st) ? s[tid - st] : 0;
        __syncthreads();
        s[tid] += t;
        __syncthreads();
    }
    int local_ex = s[tid] - v;
    if (tid == 255) g_btot[blockIdx.x] = s[255];
    __syncthreads();
    if (tid == 0) {
        __threadfence();
        atomicAdd(&g_arrive, 1);
        while (atomicAdd(&g_arrive, 0) < (int)gridDim.x) {}
        __threadfence();
    }
    __syncthreads();
    int pv = (tid < (int)blockIdx.x) ? g_btot[tid] : 0;
    s[tid] = pv; __syncthreads();
#pragma unroll
    for (int st = 128; st > 0; st >>= 1) {
        if (tid < st) s[tid] += s[tid + st];
        __syncthreads();
    }
    int prefix = s[0];
    if (i < NN) {
        g_off[i] = local_ex + prefix;
        g_rso[i] = rsqrtf((float)max(g_odeg[i], 1));
        g_rsi[i] = rsqrtf((float)max(g_ideg[i], 1));
    }
    if (i == 0) g_off[NN] = NE;
}

// blocks [0,EMBB): warp per node, ring-4 pipelined mean-pool of embT rows.
// blocks [EMBB, ...): CSR fill (uint16 src ids)
__global__ __launch_bounds__(256) void k_fillembed(const int* __restrict__ feat,
                                                   const int* __restrict__ src,
                                                   const int* __restrict__ dst) {
    if (blockIdx.x >= EMBB) {
        int e = (blockIdx.x - EMBB) * 256 + threadIdx.x;
        if (e < NE) {
            int d = dst[e];
            int p = g_off[d] + atomicAdd(&g_cur[d], 1);
            g_csr[p] = (unsigned short)src[e];
        }
        return;
    }
    int w    = (blockIdx.x * 256 + threadIdx.x) >> 5;
    int lane = threadIdx.x & 31;
    int tok = 0;
    if (lane < SEQ) tok = feat[w * SEQ + lane];
    unsigned nzm = __ballot_sync(0xffffffffu, (lane < SEQ) && (tok != 0));
    float inv_cnt = 1.0f / (float)max(__popc(nzm), 1);
    float2 lo = make_float2(0.f, 0.f), hi = make_float2(0.f, 0.f);
#pragma unroll
    for (int g = 0; g < SEQ / 4; ++g) {      // 4-in-flight groups, low regs
        uint2 r[4];
#pragma unroll
        for (int j = 0; j < 4; ++j) {
            int tk = __shfl_sync(0xffffffffu, tok, 4 * g + j);
            r[j] = g_embT[(long)tk * 32 + lane];
        }
#pragma unroll
        for (int j = 0; j < 4; ++j) acc_cg(lo, hi, r[j]);
    }
    float sc = g_rso[w] * inv_cnt;
    __half2 h01 = __floats2half2_rn(lo.x * sc, lo.y * sc);
    __half2 h23 = __floats2half2_rn(hi.x * sc, hi.y * sc);
    uint2 o;
    o.x = *(unsigned*)&h01;
    o.y = *(unsigned*)&h23;
    g_hA[(long)w * 32 + lane] = o;
}

// Layer1: warp handles 4 dst nodes. Gather with 4-way MLP unroll.
__global__ __launch_bounds__(256, 4) void k_layer1(const float* __restrict__ b1,
                                                   const float* __restrict__ W2) {
    __shared__ unsigned long long sW2p[64 * 64];      // 32KB
    for (int i = threadIdx.x; i < 64 * 64; i += 256) {
        int kp = i >> 6, c = i & 63;
        float lo = (c < CLS) ? W2[kp * CLS + c] : 0.f;
        float hi = (c < CLS) ? W2[(kp + 64) * CLS + c] : 0.f;
        sW2p[i] = pack2(lo, hi);
    }
    __syncthreads();
    int warp = threadIdx.x >> 5, lane = threadIdx.x & 31;
    float2 blo = ((const float2*)b1)[lane];
    float2 bhi = ((const float2*)(b1 + 64))[lane];
    int nwarps = gridDim.x * 8;
    for (int b = blockIdx.x * 8 + warp; b < NN / 4; b += nwarps) {
        unsigned long long pp0[4], pp1[4];
#pragma unroll
        for (int j = 0; j < 4; ++j) {
            int d = b * 4 + j;
            int beg = g_off[d], end = g_off[d + 1];
            float2 lo = make_float2(0.f, 0.f), hi = make_float2(0.f, 0.f);
            for (int base = beg; base < end; base += 32) {
                int n = min(32, end - base);
                int sid = (base + lane < end) ? (int)g_csr[base + lane] : 0;
                int t = 0;
                for (; t + 4 <= n; t += 4) {
                    int s0 = __shfl_sync(0xffffffffu, sid, t);
                    int s1 = __shfl_sync(0xffffffffu, sid, t + 1);
                    int s2 = __shfl_sync(0xffffffffu, sid, t + 2);
                    int s3 = __shfl_sync(0xffffffffu, sid, t + 3);
                    uint2 r0 = g_hA[(long)s0 * 32 + lane];
                    uint2 r1 = g_hA[(long)s1 * 32 + lane];
                    uint2 r2 = g_hA[(long)s2 * 32 + lane];
                    uint2 r3 = g_hA[(long)s3 * 32 + lane];
                    acc_cg(lo, hi, r0); acc_cg(lo, hi, r1);
                    acc_cg(lo, hi, r2); acc_cg(lo, hi, r3);
                }
                for (; t < n; ++t) {
                    int s = __shfl_sync(0xffffffffu, sid, t);
                    acc_cg(lo, hi, g_hA[(long)s * 32 + lane]);
                }
            }
            float rin = g_rsi[d];
            float ro  = g_rso[d];
            float o0 = fmaxf(lo.x * rin + blo.x, 0.f) * ro;
            float o1 = fmaxf(lo.y * rin + blo.y, 0.f) * ro;
            float o2 = fmaxf(hi.x * rin + bhi.x, 0.f) * ro;
            float o3 = fmaxf(hi.y * rin + bhi.y, 0.f) * ro;
            pp0[j] = pack2(o0, o2);
            pp1[j] = pack2(o1, o3);
        }
        unsigned long long ay[4][2];
#pragma unroll
        for (int j = 0; j < 4; ++j) { ay[j][0] = 0ull; ay[j][1] = 0ull; }
#pragma unroll 2
        for (int g = 0; g < 32; ++g) {
            unsigned long long wa0 = sW2p[(2 * g) * 64 + lane];
            unsigned long long wb0 = sW2p[(2 * g) * 64 + 32 + lane];
            unsigned long long wa1 = sW2p[(2 * g + 1) * 64 + lane];
            unsigned long long wb1 = sW2p[(2 * g + 1) * 64 + 32 + lane];
#pragma unroll
            for (int j = 0; j < 4; ++j) {
                unsigned long long c0 = __shfl_sync(0xffffffffu, pp0[j], g);
                ffma2(ay[j][0], c0, wa0); ffma2(ay[j][1], c0, wb0);
                unsigned long long c1 = __shfl_sync(0xffffffffu, pp1[j], g);
                ffma2(ay[j][0], c1, wa1); ffma2(ay[j][1], c1, wb1);
            }
        }
#pragma unroll
        for (int j = 0; j < 4; ++j) {
            int d = b * 4 + j;
            float2 v0 = unpack2(ay[j][0]);
            float2 v1 = unpack2(ay[j][1]);
            __half* yr = g_yh + (long)d * CLS;
            yr[lane] = __float2half_rn(v0.x + v0.y);
            if (lane < 8) yr[32 + lane] = __float2half_rn(v1.x + v1.y);
        }
    }
}

// Layer-2 aggregation with 4-way MLP unroll: lane<20 owns uint pair.
// Tail duty: re-zero the scratch arrays (g_odeg/g_ideg/g_cur/g_arrive) so the
// next invocation sees the same zero-state this one did (determinism invariant).
// Those arrays are not read by this kernel, so the reset is race-free.
__global__ __launch_bounds__(256, 4) void k_spmm2(const float* __restrict__ b2,
                                                  float* __restrict__ out) {
    int gi = blockIdx.x * 256 + threadIdx.x;
    if (gi < NN) { g_odeg[gi] = 0; g_ideg[gi] = 0; g_cur[gi] = 0; }
    if (gi == 0) g_arrive = 0;

    int warp = threadIdx.x >> 5, lane = threadIdx.x & 31;
    int d = blockIdx.x * 8 + warp;
    if (d >= NN) return;
    int beg = g_off[d], end = g_off[d + 1];
    float ax = 0.f, ay = 0.f;
    const unsigned* Y = (const unsigned*)g_yh;
    for (int base = beg; base < end; base += 32) {
        int n = min(32, end - base);
        int sid = (base + lane < end) ? (int)g_csr[base + lane] : 0;
        int t = 0;
        for (; t + 4 <= n; t += 4) {
            int s0 = __shfl_sync(0xffffffffu, sid, t);
            int s1 = __shfl_sync(0xffffffffu, sid, t + 1);
            int s2 = __shfl_sync(0xffffffffu, sid, t + 2);
            int s3 = __shfl_sync(0xffffffffu, sid, t + 3);
            if (lane < 20) {
                unsigned u0 = Y[s0 * 20 + lane];
                unsigned u1 = Y[s1 * 20 + lane];
                unsigned u2 = Y[s2 * 20 + lane];
                unsigned u3 = Y[s3 * 20 + lane];
                float2 f;
                f = __half22float2(*(__half2*)&u0); ax += f.x; ay += f.y;
                f = __half22float2(*(__half2*)&u1); ax += f.x; ay += f.y;
                f = __half22float2(*(__half2*)&u2); ax += f.x; ay += f.y;
                f = __half22float2(*(__half2*)&u3); ax += f.x; ay += f.y;
            }
        }
        for (; t < n; ++t) {
            int s = __shfl_sync(0xffffffffu, sid, t);
            if (lane < 20) {
                unsigned u = Y[s * 20 + lane];
                float2 f = __half22float2(*(__half2*)&u);
                ax += f.x; ay += f.y;
            }
        }
    }
    if (lane < 20) {
        float rin = g_rsi[d];
        float2 bp = ((const float2*)b2)[lane];
        ((float2*)(out + (long)d * CLS))[lane] =
            make_float2(ax * rin + bp.x, ay * rin + bp.y);
    }
}

extern "C" void kernel_launch(void* const* d_in, const int* in_sizes, int n_in,
                              void* d_out, int out_size) {
    const int*   feat = (const int*)  d_in[0];
    const int*   src  = (const int*)  d_in[1];
    const int*   dst  = (const int*)  d_in[2];
    const float* emb  = (const float*)d_in[3];
    const float* W1   = (const float*)d_in[4];
    const float* b1   = (const float*)d_in[5];
    const float* W2   = (const float*)d_in[6];
    const float* b2   = (const float*)d_in[7];
    float* out = (float*)d_out;

    const int smemT = 64 * 128 * 8;   // 64KB
    cudaFuncSetAttribute(k_tabledeg,
                         cudaFuncAttributeMaxDynamicSharedMemorySize, smemT);

    k_tabledeg<<<GEMMB + DEGB, 256, smemT>>>(emb, W1, src, dst);
    k_scan<<<NB, 256>>>();
    k_fillembed<<<EMBB + DEGB, 256>>>(feat, src, dst);
    k_layer1<<<592, 256>>>(b1, W2);   // 4 blocks/SM
    k_spmm2<<<NN / 8, 256>>>(b2, out);
}